// round 1
// baseline (speedup 1.0000x reference)
#include <cuda_runtime.h>
#include <math.h>

#define N_TOKENS 131072
#define EMBED    64
#define K_CODES  1024
#define TPB      256
#define CHUNK    128   // codes per shared-memory chunk (32 KB)

// Output layout (float32, in reference return order):
//   [0]                      loss (scalar)
//   [1 .. 1+N*D)             quantized_st  (== weight[idx], STE is numeric no-op)
//   [1+N*D]                  perplexity (scalar)
//   [2+N*D .. 2+N*D+N*K)     encodings one-hot
#define OFF_Q    1
#define OFF_P    (1 + (size_t)N_TOKENS * EMBED)
#define OFF_E    (2 + (size_t)N_TOKENS * EMBED)

__device__ float  g_ncb[K_CODES * EMBED];   // L2-normalized codebook
__device__ int    g_hist[K_CODES];
__device__ double g_loss;

// ---------------------------------------------------------------------------
// Prep: normalize codebook rows, zero histogram + loss accumulator.
// ---------------------------------------------------------------------------
__global__ void k_prep(const float* __restrict__ weight)
{
    int k = blockIdx.x * blockDim.x + threadIdx.x;
    if (k == 0) g_loss = 0.0;
    if (k < K_CODES) {
        g_hist[k] = 0;
        const float* w = weight + k * EMBED;
        float s = 0.f;
#pragma unroll
        for (int i = 0; i < EMBED; ++i) { float v = w[i]; s = fmaf(v, v, s); }
        float n  = sqrtf(s);
        float dn = fmaxf(n, 1e-12f);
        float* o = g_ncb + k * EMBED;
#pragma unroll
        for (int i = 0; i < EMBED; ++i) o[i] = w[i] / dn;
    }
}

// ---------------------------------------------------------------------------
// Main: per-token argmax of cosine similarity via packed fp32x2 FMA (FFMA2),
// then fused epilogue: quantized gather+store, one-hot scatter, histogram,
// loss partial sum.
// ---------------------------------------------------------------------------
__global__ void __launch_bounds__(TPB, 2) k_main(
    const float* __restrict__ inputs,
    const float* __restrict__ weight,
    float* __restrict__ out)
{
    __shared__ float cbs[CHUNK * EMBED];   // 32 KB chunk of normalized codebook
    __shared__ int   s_best[TPB];

    const int tid = threadIdx.x;
    const int t   = blockIdx.x * TPB + tid;   // one token per thread

    // ---- load z, compute norm, normalize, pack into 32 x f32x2 regs ----
    float zv[EMBED];
    {
        const float4* zin = (const float4*)(inputs + (size_t)t * EMBED);
        float s = 0.f;
#pragma unroll
        for (int i = 0; i < 16; ++i) {
            float4 v = zin[i];
            zv[4*i+0] = v.x; zv[4*i+1] = v.y; zv[4*i+2] = v.z; zv[4*i+3] = v.w;
            s = fmaf(v.x, v.x, s); s = fmaf(v.y, v.y, s);
            s = fmaf(v.z, v.z, s); s = fmaf(v.w, v.w, s);
        }
        float n  = sqrtf(s);
        float dn = fmaxf(n, 1e-12f);
#pragma unroll
        for (int i = 0; i < EMBED; ++i) zv[i] = zv[i] / dn;
    }
    unsigned long long zp[32];
#pragma unroll
    for (int i = 0; i < 32; ++i)
        asm("mov.b64 %0, {%1, %2};" : "=l"(zp[i]) : "f"(zv[2*i]), "f"(zv[2*i+1]));

    // ---- score all 1024 codes, track running argmax (first-occurrence) ----
    float bestv = -1e30f;
    int   bidx  = 0;

    for (int ch = 0; ch < K_CODES / CHUNK; ++ch) {
        __syncthreads();
        {   // cooperative load of 128 codes into shared
            const float4* src = (const float4*)(g_ncb + (size_t)ch * CHUNK * EMBED);
            float4*       dst = (float4*)cbs;
#pragma unroll
            for (int i = 0; i < (CHUNK * EMBED / 4) / TPB; ++i)
                dst[tid + i * TPB] = src[tid + i * TPB];
        }
        __syncthreads();

#pragma unroll 2
        for (int k = 0; k < CHUNK; ++k) {
            const unsigned long long* cp =
                (const unsigned long long*)(cbs + k * EMBED);
            unsigned long long a0 = 0ull, a1 = 0ull;  // packed (0,0)
#pragma unroll
            for (int i = 0; i < 32; i += 2) {
                asm("fma.rn.f32x2 %0, %1, %2, %0;" : "+l"(a0) : "l"(zp[i]),   "l"(cp[i]));
                asm("fma.rn.f32x2 %0, %1, %2, %0;" : "+l"(a1) : "l"(zp[i+1]), "l"(cp[i+1]));
            }
            float lo0, hi0, lo1, hi1;
            asm("mov.b64 {%0, %1}, %2;" : "=f"(lo0), "=f"(hi0) : "l"(a0));
            asm("mov.b64 {%0, %1}, %2;" : "=f"(lo1), "=f"(hi1) : "l"(a1));
            float sc = (lo0 + hi0) + (lo1 + hi1);
            if (sc > bestv) { bestv = sc; bidx = ch * CHUNK + k; }
        }
    }

    s_best[tid] = bidx;
    __syncthreads();

    // ---- cooperative epilogue: each warp handles its 32 tokens ----
    const int warpId  = tid >> 5;
    const int lane    = tid & 31;
    const int tokBase = blockIdx.x * TPB + warpId * 32;

    float* out_q   = out + OFF_Q;
    float* out_enc = out + OFF_E;

    float lsum = 0.f;
#pragma unroll 1
    for (int j = 0; j < 32; ++j) {
        int tok = tokBase + j;
        int bi  = s_best[warpId * 32 + j];
        const float* wr = weight + (size_t)bi  * EMBED;
        const float* xr = inputs + (size_t)tok * EMBED;
        float q0 = wr[lane], q1 = wr[lane + 32];
        float x0 = xr[lane], x1 = xr[lane + 32];
        out_q[(size_t)tok * EMBED + lane]      = q0;
        out_q[(size_t)tok * EMBED + lane + 32] = q1;
        float d0 = q0 - x0, d1 = q1 - x1;
        lsum = fmaf(d0, d0, lsum);
        lsum = fmaf(d1, d1, lsum);
    }

    {   // one-hot scatter + histogram: one token per lane
        int tok = tokBase + lane;
        int bi  = s_best[warpId * 32 + lane];
        out_enc[(size_t)tok * K_CODES + bi] = 1.0f;
        atomicAdd(&g_hist[bi], 1);
    }

#pragma unroll
    for (int o = 16; o > 0; o >>= 1)
        lsum += __shfl_xor_sync(0xffffffffu, lsum, o);
    if (lane == 0) atomicAdd(&g_loss, (double)lsum);
}

// ---------------------------------------------------------------------------
// Final: loss scalar + perplexity from histogram.
// ---------------------------------------------------------------------------
__global__ void k_final(float* __restrict__ out)
{
    __shared__ double sh[32];
    int tid  = threadIdx.x;
    int lane = tid & 31, wid = tid >> 5;

    float p    = (float)g_hist[tid] / (float)N_TOKENS;
    float term = p * logf(p + 1e-10f);
    double v   = (double)term;

#pragma unroll
    for (int o = 16; o > 0; o >>= 1)
        v += __shfl_xor_sync(0xffffffffu, v, o);
    if (lane == 0) sh[wid] = v;
    __syncthreads();
    if (tid == 0) {
        double tot = 0.0;
#pragma unroll
        for (int w = 0; w < 32; ++w) tot += sh[w];
        out[0]     = (float)(1.25 * g_loss / (double)((size_t)N_TOKENS * EMBED));
        out[OFF_P] = expf(-(float)tot);
    }
}

// ---------------------------------------------------------------------------
extern "C" void kernel_launch(void* const* d_in, const int* in_sizes, int n_in,
                              void* d_out, int out_size)
{
    const float* inputs = (const float*)d_in[0];
    const float* weight = (const float*)d_in[1];
    float*       out    = (float*)d_out;

    // zero the whole output (encodings one-hot background, scalars, etc.)
    cudaMemsetAsync(d_out, 0, (size_t)out_size * sizeof(float));

    k_prep <<<K_CODES / 256, 256>>>(weight);
    k_main <<<N_TOKENS / TPB, TPB>>>(inputs, weight, out);
    k_final<<<1, K_CODES>>>(out);
}

// round 3
// speedup vs baseline: 1.3621x; 1.3621x over previous
#include <cuda_runtime.h>
#include <math.h>

#define N_TOKENS 131072
#define EMBED    64
#define K_CODES  1024
#define TPB      256
#define TOK_TILE 64      // tokens per block
#define CODE_TILE 64     // codes per shared stage
#define N_CT     (K_CODES / CODE_TILE)   // 16 code-tiles
#define KP       (EMBED / 2)             // 32 k-pairs

// Output layout (float32, reference return order):
//   [0] loss | [1 .. 1+N*D) quantized_st | [1+N*D] perplexity | then encodings
#define OFF_Q    1
#define OFF_P    (1 + (size_t)N_TOKENS * EMBED)
#define OFF_E    (2 + (size_t)N_TOKENS * EMBED)

__device__ float  g_ncb[K_CODES * EMBED];   // L2-normalized codebook
__device__ int    g_hist[K_CODES];
__device__ double g_loss;

#define FMA2(acc, a, b) \
    asm("fma.rn.f32x2 %0, %1, %2, %0;" : "+l"(acc) : "l"(a), "l"(b))

// ---------------------------------------------------------------------------
// Prep: warp-per-code normalize; zero histogram + loss.   <<<128, 256>>>
// ---------------------------------------------------------------------------
__global__ void k_prep(const float* __restrict__ weight)
{
    const int tid  = threadIdx.x;
    const int lane = tid & 31;
    const int w    = blockIdx.x * 8 + (tid >> 5);      // code index 0..1023
    const int gid  = blockIdx.x * 256 + tid;

    if (gid == 0) g_loss = 0.0;
    if (gid < K_CODES) g_hist[gid] = 0;

    const float* wr = weight + (size_t)w * EMBED;
    float a = wr[lane], b = wr[lane + 32];
    float s = fmaf(a, a, b * b);
#pragma unroll
    for (int o = 16; o > 0; o >>= 1)
        s += __shfl_xor_sync(0xffffffffu, s, o);
    float dn = fmaxf(sqrtf(s), 1e-12f);
    g_ncb[(size_t)w * EMBED + lane]      = a / dn;
    g_ncb[(size_t)w * EMBED + lane + 32] = b / dn;
}

// ---------------------------------------------------------------------------
// Main: register-tiled FFMA2 score GEMM + argmax + fused epilogue
// (quantized gather, full one-hot row write, loss, histogram).
// Grid: N/64 blocks x 256 threads. Thread tile: 4 tokens x 4 codes.
// ---------------------------------------------------------------------------
__global__ void __launch_bounds__(TPB, 3) k_main(
    const float* __restrict__ inputs,
    const float* __restrict__ weight,
    float* __restrict__ out)
{
    // zs[kp][2*token + (k&1)] : normalized z, k-pairs packed per token
    __shared__ float zs[KP][132];                 // 16.9 KB (132 = 2*64+4 pad)
    __shared__ float cbs[CODE_TILE * 66];         // 16.9 KB (stride 66)
    __shared__ int   s_best[TOK_TILE];

    const int tid = threadIdx.x;
    const int ty  = tid >> 4;        // 0..15 -> token group (4 tokens each)
    const int tx  = tid & 15;        // 0..15 -> code lane (4 codes, stride 16)
    const int tokBase = blockIdx.x * TOK_TILE;

    // ---- stage z: thread handles token tid/4, quarter tid%4 (16 floats) ----
    {
        const int tt = tid >> 2, q = tid & 3;
        const float4* zin =
            (const float4*)(inputs + (size_t)(tokBase + tt) * EMBED) + q * 4;
        float4 v0 = zin[0], v1 = zin[1], v2 = zin[2], v3 = zin[3];
        float s = 0.f;
        s = fmaf(v0.x, v0.x, s); s = fmaf(v0.y, v0.y, s);
        s = fmaf(v0.z, v0.z, s); s = fmaf(v0.w, v0.w, s);
        s = fmaf(v1.x, v1.x, s); s = fmaf(v1.y, v1.y, s);
        s = fmaf(v1.z, v1.z, s); s = fmaf(v1.w, v1.w, s);
        s = fmaf(v2.x, v2.x, s); s = fmaf(v2.y, v2.y, s);
        s = fmaf(v2.z, v2.z, s); s = fmaf(v2.w, v2.w, s);
        s = fmaf(v3.x, v3.x, s); s = fmaf(v3.y, v3.y, s);
        s = fmaf(v3.z, v3.z, s); s = fmaf(v3.w, v3.w, s);
        s += __shfl_xor_sync(0xffffffffu, s, 1);
        s += __shfl_xor_sync(0xffffffffu, s, 2);
        float dn = fmaxf(sqrtf(s), 1e-12f);
        float zv[16];
        zv[0]=v0.x; zv[1]=v0.y; zv[2]=v0.z; zv[3]=v0.w;
        zv[4]=v1.x; zv[5]=v1.y; zv[6]=v1.z; zv[7]=v1.w;
        zv[8]=v2.x; zv[9]=v2.y; zv[10]=v2.z; zv[11]=v2.w;
        zv[12]=v3.x; zv[13]=v3.y; zv[14]=v3.z; zv[15]=v3.w;
#pragma unroll
        for (int j = 0; j < 8; ++j) {
            float2 p = make_float2(zv[2*j] / dn, zv[2*j+1] / dn);
            *(float2*)&zs[q * 8 + j][2 * tt] = p;
        }
    }
    __syncthreads();

    float bestv[4]; int bidx[4];
#pragma unroll
    for (int t = 0; t < 4; ++t) { bestv[t] = -1e30f; bidx[t] = 0; }

    const ulonglong2* zrowA = (const ulonglong2*)&zs[0][8 * ty];      // t0,t1
    const ulonglong2* zrowB = (const ulonglong2*)&zs[0][8 * ty + 4];  // t2,t3
    const unsigned long long* crow =
        (const unsigned long long*)&cbs[tx * 66];

    for (int ct = 0; ct < N_CT; ++ct) {
        const int codeBase = ct * CODE_TILE;
        __syncthreads();
        {   // stage 64 codes into cbs (stride 66)
            const int cc = tid >> 2, q = tid & 3;
            const float4* src =
                (const float4*)(g_ncb + (size_t)(codeBase + cc) * EMBED) + q * 4;
            float* dst = &cbs[cc * 66 + q * 16];
            float4 a = src[0], b = src[1], c = src[2], d = src[3];
            ((float2*)dst)[0] = make_float2(a.x, a.y);
            ((float2*)dst)[1] = make_float2(a.z, a.w);
            ((float2*)dst)[2] = make_float2(b.x, b.y);
            ((float2*)dst)[3] = make_float2(b.z, b.w);
            ((float2*)dst)[4] = make_float2(c.x, c.y);
            ((float2*)dst)[5] = make_float2(c.z, c.w);
            ((float2*)dst)[6] = make_float2(d.x, d.y);
            ((float2*)dst)[7] = make_float2(d.z, d.w);
        }
        __syncthreads();

        unsigned long long acc[16];
#pragma unroll
        for (int i = 0; i < 16; ++i) acc[i] = 0ull;

#pragma unroll 8
        for (int kp = 0; kp < KP; ++kp) {
            ulonglong2 za = zrowA[kp * 33];   // 33 ulonglong2 = 132 floats
            ulonglong2 zb = zrowB[kp * 33];
            unsigned long long c0 = crow[0 * 528 + kp];  // 528 = 16*66/2
            unsigned long long c1 = crow[1 * 528 + kp];
            unsigned long long c2 = crow[2 * 528 + kp];
            unsigned long long c3 = crow[3 * 528 + kp];
            FMA2(acc[ 0], za.x, c0); FMA2(acc[ 1], za.x, c1);
            FMA2(acc[ 2], za.x, c2); FMA2(acc[ 3], za.x, c3);
            FMA2(acc[ 4], za.y, c0); FMA2(acc[ 5], za.y, c1);
            FMA2(acc[ 6], za.y, c2); FMA2(acc[ 7], za.y, c3);
            FMA2(acc[ 8], zb.x, c0); FMA2(acc[ 9], zb.x, c1);
            FMA2(acc[10], zb.x, c2); FMA2(acc[11], zb.x, c3);
            FMA2(acc[12], zb.y, c0); FMA2(acc[13], zb.y, c1);
            FMA2(acc[14], zb.y, c2); FMA2(acc[15], zb.y, c3);
        }

#pragma unroll
        for (int t = 0; t < 4; ++t) {
#pragma unroll
            for (int j = 0; j < 4; ++j) {
                float lo, hi;
                asm("mov.b64 {%0, %1}, %2;" : "=f"(lo), "=f"(hi)
                    : "l"(acc[t * 4 + j]));
                float sc = lo + hi;
                int code = codeBase + j * 16 + tx;
                if (sc > bestv[t]) { bestv[t] = sc; bidx[t] = code; }
            }
        }
    }

    // ---- argmax reduce across the 16 tx-lanes sharing each token ----
#pragma unroll
    for (int t = 0; t < 4; ++t) {
        float v = bestv[t]; int i = bidx[t];
#pragma unroll
        for (int o = 8; o > 0; o >>= 1) {
            float v2 = __shfl_xor_sync(0xffffffffu, v, o);
            int   i2 = __shfl_xor_sync(0xffffffffu, i, o);
            if (v2 > v || (v2 == v && i2 < i)) { v = v2; i = i2; }
        }
        if (tx == 0) s_best[ty * 4 + t] = i;
    }
    __syncthreads();

    // ---- fused epilogue: 8 warps x 8 tokens ----
    const int warpId = tid >> 5;
    const int lane   = tid & 31;
    float* out_q   = out + OFF_Q;
    float* out_enc = out + OFF_E;

    float lsum = 0.f;
#pragma unroll 1
    for (int jj = 0; jj < 8; ++jj) {
        const int lt  = warpId * 8 + jj;
        const int tok = tokBase + lt;
        const int bi  = s_best[lt];
        const float* wr = weight + (size_t)bi  * EMBED;
        const float* xr = inputs + (size_t)tok * EMBED;
        float q0 = wr[lane], q1 = wr[lane + 32];
        float x0 = xr[lane], x1 = xr[lane + 32];
        out_q[(size_t)tok * EMBED + lane]      = q0;
        out_q[(size_t)tok * EMBED + lane + 32] = q1;
        float d0 = q0 - x0, d1 = q1 - x1;
        lsum = fmaf(d0, d0, lsum);
        lsum = fmaf(d1, d1, lsum);

        // full one-hot row (zeros + the single 1.0).
        // NOTE: out_enc is float-offset ≡ 2 (mod 4) -> only 8B-aligned, so
        // float2 stores (STG.64) — float4 here traps with misaligned address.
        float2* erow = (float2*)(out_enc + (size_t)tok * K_CODES);
#pragma unroll
        for (int c2 = 0; c2 < 16; ++c2) {
            int f2  = lane + 32 * c2;
            int rel = bi - 2 * f2;
            float2 e;
            e.x = (rel == 0) ? 1.f : 0.f;
            e.y = (rel == 1) ? 1.f : 0.f;
            erow[f2] = e;
        }
    }

    if (lane < 8) atomicAdd(&g_hist[s_best[warpId * 8 + lane]], 1);

#pragma unroll
    for (int o = 16; o > 0; o >>= 1)
        lsum += __shfl_xor_sync(0xffffffffu, lsum, o);
    if (lane == 0) atomicAdd(&g_loss, (double)lsum);
}

// ---------------------------------------------------------------------------
// Final: loss scalar + perplexity from histogram.   <<<1, 1024>>>
// ---------------------------------------------------------------------------
__global__ void k_final(float* __restrict__ out)
{
    __shared__ double sh[32];
    int tid  = threadIdx.x;
    int lane = tid & 31, wid = tid >> 5;

    float p    = (float)g_hist[tid] / (float)N_TOKENS;
    float term = p * logf(p + 1e-10f);
    double v   = (double)term;

#pragma unroll
    for (int o = 16; o > 0; o >>= 1)
        v += __shfl_xor_sync(0xffffffffu, v, o);
    if (lane == 0) sh[wid] = v;
    __syncthreads();
    if (tid == 0) {
        double tot = 0.0;
#pragma unroll
        for (int w = 0; w < 32; ++w) tot += sh[w];
        out[0]     = (float)(1.25 * g_loss / (double)((size_t)N_TOKENS * EMBED));
        out[OFF_P] = expf(-(float)tot);
    }
}

// ---------------------------------------------------------------------------
extern "C" void kernel_launch(void* const* d_in, const int* in_sizes, int n_in,
                              void* d_out, int out_size)
{
    const float* inputs = (const float*)d_in[0];
    const float* weight = (const float*)d_in[1];
    float*       out    = (float*)d_out;

    k_prep <<<K_CODES / 8, 256>>>(weight);          // 128 blocks
    k_main <<<N_TOKENS / TOK_TILE, TPB>>>(inputs, weight, out);
    k_final<<<1, K_CODES>>>(out);
}

// round 6
// speedup vs baseline: 1.7922x; 1.3158x over previous
#include <cuda_runtime.h>
#include <cuda_bf16.h>
#include <math.h>
#include <stdint.h>

#define N_TOKENS 131072
#define EMBED    64
#define K_CODES  1024
#define TOK_TILE 128           // tokens per CTA
#define NC       128           // codes per smem chunk
#define NCHUNK   (K_CODES / NC)
#define THREADS  256
#define PLANE_SZ 16384         // 128 rows x 128 B
#define SMEM_DYN (3 * PLANE_SZ + 1024)

// Output layout (float32, reference return order):
#define OFF_Q 1
#define OFF_P (1 + (size_t)N_TOKENS * EMBED)
#define OFF_E (2 + (size_t)N_TOKENS * EMBED)

__device__ __nv_bfloat16 g_cb[3][K_CODES * EMBED];  // codebook bf16 split planes
__device__ int    g_hist[K_CODES];
__device__ double g_loss;

#define SW128(o) ((o) ^ (((o) >> 3) & 0x70))

__device__ __forceinline__ uint32_t smem_u32(const void* p) {
    uint32_t a;
    asm("{ .reg .u64 t; cvta.to.shared.u64 t, %1; cvt.u32.u64 %0, t; }"
        : "=r"(a) : "l"(p));
    return a;
}
__device__ __forceinline__ void ldsm4(uint32_t& r0, uint32_t& r1,
                                      uint32_t& r2, uint32_t& r3, uint32_t a) {
    asm volatile("ldmatrix.sync.aligned.m8n8.x4.shared.b16 {%0,%1,%2,%3}, [%4];"
                 : "=r"(r0), "=r"(r1), "=r"(r2), "=r"(r3) : "r"(a));
}
__device__ __forceinline__ void mma16816(float* d, const uint32_t* a,
                                         const uint32_t* b) {
    asm volatile(
        "mma.sync.aligned.m16n8k16.row.col.f32.bf16.bf16.f32 "
        "{%0,%1,%2,%3}, {%4,%5,%6,%7}, {%8,%9}, {%0,%1,%2,%3};"
        : "+f"(d[0]), "+f"(d[1]), "+f"(d[2]), "+f"(d[3])
        : "r"(a[0]), "r"(a[1]), "r"(a[2]), "r"(a[3]), "r"(b[0]), "r"(b[1]));
}

// ---------------------------------------------------------------------------
// Prep: normalize codebook, 3-way bf16 split; zero hist + loss.  <<<128,256>>>
// ---------------------------------------------------------------------------
__global__ void k_prep(const float* __restrict__ weight)
{
    const int tid  = threadIdx.x;
    const int lane = tid & 31;
    const int k    = blockIdx.x * 8 + (tid >> 5);
    const int gid  = blockIdx.x * 256 + tid;

    if (gid == 0) g_loss = 0.0;
    if (gid < K_CODES) g_hist[gid] = 0;

    const float* wr = weight + (size_t)k * EMBED;
    float a = wr[lane], b = wr[lane + 32];
    float s = fmaf(a, a, b * b);
#pragma unroll
    for (int o = 16; o > 0; o >>= 1) s += __shfl_xor_sync(0xffffffffu, s, o);
    float dn = fmaxf(sqrtf(s), 1e-12f);

#pragma unroll
    for (int h = 0; h < 2; ++h) {
        int d = lane + 32 * h;
        float v = (h ? b : a) / dn;
        __nv_bfloat16 vh = __float2bfloat16_rn(v);
        float r1 = v - __bfloat162float(vh);
        __nv_bfloat16 vm = __float2bfloat16_rn(r1);
        float r2 = r1 - __bfloat162float(vm);
        __nv_bfloat16 vl = __float2bfloat16_rn(r2);
        g_cb[0][(size_t)k * EMBED + d] = vh;
        g_cb[1][(size_t)k * EMBED + d] = vm;
        g_cb[2][(size_t)k * EMBED + d] = vl;
    }
}

// ---------------------------------------------------------------------------
// Main: bf16x3 split-GEMM via mma.sync (6 terms, f32 accum in registers),
// per-token argmax, fused epilogue.  <<<1024, 256, SMEM_DYN>>>
// Warp w owns tokens w*16..w*16+15; A fragments live in registers.
// ---------------------------------------------------------------------------
extern __shared__ char smem_raw[];

__global__ void __launch_bounds__(THREADS, 2)
k_main(const float* __restrict__ inputs,
       const float* __restrict__ weight,
       float* __restrict__ out)
{
    __shared__ int s_best[TOK_TILE];

    char* smem = (char*)(((uintptr_t)smem_raw + 1023) & ~(uintptr_t)1023);
    const uint32_t smb = smem_u32(smem);
    const int tid = threadIdx.x;
    const int wid = tid >> 5;
    const int lane = tid & 31;
    const int tokBase = blockIdx.x * TOK_TILE;

    // ---- phase 1: stage A (normalize, 3-way bf16 split) into SW128 smem ----
    {
        const int t = tid >> 1, h = tid & 1;       // 2 threads per token
        const float4* zp = (const float4*)(inputs + (size_t)(tokBase + t) * EMBED + h * 32);
        float z[32];
        float s = 0.f;
#pragma unroll
        for (int i = 0; i < 8; ++i) {
            float4 v = zp[i];
            z[4*i+0]=v.x; z[4*i+1]=v.y; z[4*i+2]=v.z; z[4*i+3]=v.w;
            s = fmaf(v.x,v.x,s); s = fmaf(v.y,v.y,s);
            s = fmaf(v.z,v.z,s); s = fmaf(v.w,v.w,s);
        }
        s += __shfl_xor_sync(0xffffffffu, s, 1);
        float dn = fmaxf(sqrtf(s), 1e-12f);
#pragma unroll
        for (int g = 0; g < 4; ++g) {              // 4 x 16B granules
            unsigned short uh[8], um[8], ul[8];
#pragma unroll
            for (int j = 0; j < 8; ++j) {
                float v = z[g * 8 + j] / dn;
                __nv_bfloat16 vh = __float2bfloat16_rn(v);
                float r1 = v - __bfloat162float(vh);
                __nv_bfloat16 vm = __float2bfloat16_rn(r1);
                float r2 = r1 - __bfloat162float(vm);
                __nv_bfloat16 vl = __float2bfloat16_rn(r2);
                uh[j] = __bfloat16_as_ushort(vh);
                um[j] = __bfloat16_as_ushort(vm);
                ul[j] = __bfloat16_as_ushort(vl);
            }
            uint32_t off = SW128((uint32_t)(t * 128 + h * 64 + g * 16));
            *(uint4*)(smem + 0*PLANE_SZ + off) = *(uint4*)uh;
            *(uint4*)(smem + 1*PLANE_SZ + off) = *(uint4*)um;
            *(uint4*)(smem + 2*PLANE_SZ + off) = *(uint4*)ul;
        }
    }
    __syncthreads();

    // ---- load A fragments into registers (3 planes x 4 k-steps x 4 regs) ----
    const int mi = lane >> 3, r8 = lane & 7;
    const int tig = lane & 3, gid = lane >> 2;
    uint32_t af[3][16];
    {
        const int row = wid * 16 + (mi & 1) * 8 + r8;
        const uint32_t rowBase = smb + (uint32_t)row * 128;
#pragma unroll
        for (int p = 0; p < 3; ++p)
#pragma unroll
            for (int s = 0; s < 4; ++s) {
                int gran = 2 * s + (mi >> 1);
                ldsm4(af[p][4*s], af[p][4*s+1], af[p][4*s+2], af[p][4*s+3],
                      rowBase + p * PLANE_SZ + (uint32_t)((gran ^ r8) * 16));
            }
    }

    float best0v = -2e30f, best1v = -2e30f;
    int   best0i = 0,      best1i = 0;

#pragma unroll 1
    for (int ct = 0; ct < NCHUNK; ++ct) {
        __syncthreads();   // A frags read (ct==0) / previous chunk consumed
        for (int i = tid; i < 3 * NC * 8; i += THREADS) {
            int pl = i >> 10, rem = i & 1023, rr = rem >> 3, g = rem & 7;
            uint4 v = *(const uint4*)(&g_cb[pl][(size_t)(ct * NC + rr) * EMBED + g * 8]);
            *(uint4*)(smem + pl * PLANE_SZ + rr * 128 + ((g ^ (rr & 7)) * 16)) = v;
        }
        __syncthreads();

#pragma unroll 1
        for (int n0 = 0; n0 < NC; n0 += 8) {
            uint32_t bf[3][8];
            const uint32_t bBase = smb + (uint32_t)((n0 + r8) * 128);
#pragma unroll
            for (int p = 0; p < 3; ++p) {
                ldsm4(bf[p][0], bf[p][1], bf[p][2], bf[p][3],
                      bBase + p * PLANE_SZ + (uint32_t)((mi ^ r8) * 16));
                ldsm4(bf[p][4], bf[p][5], bf[p][6], bf[p][7],
                      bBase + p * PLANE_SZ + (uint32_t)(((4 + mi) ^ r8) * 16));
            }
            float accA[4] = {0,0,0,0}, accB[4] = {0,0,0,0}, accC[4] = {0,0,0,0};
#pragma unroll
            for (int s = 0; s < 4; ++s) {
                mma16816(accA, &af[0][4*s], &bf[0][2*s]);   // h*h
                mma16816(accB, &af[0][4*s], &bf[1][2*s]);   // h*m
                mma16816(accC, &af[1][4*s], &bf[0][2*s]);   // m*h
                mma16816(accA, &af[1][4*s], &bf[1][2*s]);   // m*m
                mma16816(accB, &af[0][4*s], &bf[2][2*s]);   // h*l
                mma16816(accC, &af[2][4*s], &bf[0][2*s]);   // l*h
            }
            float s0 = accA[0] + accB[0] + accC[0];
            float s1 = accA[1] + accB[1] + accC[1];
            float s2 = accA[2] + accB[2] + accC[2];
            float s3 = accA[3] + accB[3] + accC[3];
            int c0 = ct * NC + n0 + 2 * tig;
            if (s0 > best0v) { best0v = s0; best0i = c0;     }
            if (s1 > best0v) { best0v = s1; best0i = c0 + 1; }
            if (s2 > best1v) { best1v = s2; best1i = c0;     }
            if (s3 > best1v) { best1v = s3; best1i = c0 + 1; }
        }
    }

    // ---- argmax reduce across the 4 tig-lanes sharing each token row ----
#pragma unroll
    for (int o = 1; o <= 2; o <<= 1) {
        float v0 = __shfl_xor_sync(0xffffffffu, best0v, o);
        int   i0 = __shfl_xor_sync(0xffffffffu, best0i, o);
        if (v0 > best0v || (v0 == best0v && i0 < best0i)) { best0v = v0; best0i = i0; }
        float v1 = __shfl_xor_sync(0xffffffffu, best1v, o);
        int   i1 = __shfl_xor_sync(0xffffffffu, best1i, o);
        if (v1 > best1v || (v1 == best1v && i1 < best1i)) { best1v = v1; best1i = i1; }
    }
    if (tig == 0) {
        s_best[wid * 16 + gid]     = best0i;
        s_best[wid * 16 + 8 + gid] = best1i;
    }
    __syncthreads();

    // ---- fused epilogue: 8 warps x 16 tokens ----
    float* out_q   = out + OFF_Q;
    float* out_enc = out + OFF_E;
    float lsum = 0.f;

#pragma unroll 1
    for (int jj = 0; jj < 16; ++jj) {
        const int lt  = wid * 16 + jj;
        const int tok = tokBase + lt;
        const int bi  = s_best[lt];
        const float* wr = weight + (size_t)bi  * EMBED;
        const float* xr = inputs + (size_t)tok * EMBED;
        float q0 = wr[lane], q1 = wr[lane + 32];
        float x0 = xr[lane], x1 = xr[lane + 32];
        out_q[(size_t)tok * EMBED + lane]      = q0;
        out_q[(size_t)tok * EMBED + lane + 32] = q1;
        float d0 = q0 - x0, d1 = q1 - x1;
        lsum = fmaf(d0, d0, lsum);
        lsum = fmaf(d1, d1, lsum);

        // encodings base is float-offset ≡ 2 (mod 4) -> 8B-aligned: float2 only
        float2* erow = (float2*)(out_enc + (size_t)tok * K_CODES);
#pragma unroll
        for (int i = 0; i < 16; ++i) {
            int f2  = lane + 32 * i;
            int rel = bi - 2 * f2;
            float2 e;
            e.x = (rel == 0) ? 1.f : 0.f;
            e.y = (rel == 1) ? 1.f : 0.f;
            erow[f2] = e;
        }
    }

    if (lane == 0) {
        for (int jj = 0; jj < 16; ++jj)
            atomicAdd(&g_hist[s_best[wid * 16 + jj]], 1);
    }
#pragma unroll
    for (int o = 16; o > 0; o >>= 1)
        lsum += __shfl_xor_sync(0xffffffffu, lsum, o);
    if (lane == 0) atomicAdd(&g_loss, (double)lsum);
}

// ---------------------------------------------------------------------------
// Final: loss scalar + perplexity from histogram.   <<<1, 1024>>>
// ---------------------------------------------------------------------------
__global__ void k_final(float* __restrict__ out)
{
    __shared__ double sh[32];
    int tid = threadIdx.x, lane = tid & 31, w = tid >> 5;

    float p  = (float)g_hist[tid] / (float)N_TOKENS;
    double v = (double)(p * logf(p + 1e-10f));
#pragma unroll
    for (int o = 16; o > 0; o >>= 1) v += __shfl_xor_sync(0xffffffffu, v, o);
    if (lane == 0) sh[w] = v;
    __syncthreads();
    if (tid == 0) {
        double tot = 0.0;
#pragma unroll
        for (int i = 0; i < 32; ++i) tot += sh[i];
        out[0]     = (float)(1.25 * g_loss / (double)((size_t)N_TOKENS * EMBED));
        out[OFF_P] = expf(-(float)tot);
    }
}

// ---------------------------------------------------------------------------
extern "C" void kernel_launch(void* const* d_in, const int* in_sizes, int n_in,
                              void* d_out, int out_size)
{
    const float* inputs = (const float*)d_in[0];
    const float* weight = (const float*)d_in[1];
    float*       out    = (float*)d_out;

    cudaFuncSetAttribute(k_main, cudaFuncAttributeMaxDynamicSharedMemorySize,
                         SMEM_DYN);

    k_prep <<<K_CODES / 8, 256>>>(weight);
    k_main <<<N_TOKENS / TOK_TILE, THREADS, SMEM_DYN>>>(inputs, weight, out);
    k_final<<<1, K_CODES>>>(out);
}

// round 7
// speedup vs baseline: 2.0066x; 1.1196x over previous
#include <cuda_runtime.h>
#include <cuda_fp16.h>
#include <math.h>
#include <stdint.h>

#define N_TOKENS 131072
#define EMBED    64
#define K_CODES  1024
#define TOK_TILE 128           // tokens per CTA
#define NC       128           // codes per smem chunk
#define NCHUNK   (K_CODES / NC)
#define THREADS  256
#define PLANE_SZ 16384         // 128 rows x 128 B
#define SCRATCH  (2 * PLANE_SZ)            // fallback z scratch (8 warps x 64 f32)
#define SMEM_DYN (2 * PLANE_SZ + 2048 + 1024)
#define MARGIN   8e-6f         // > 8x rigorous fp16-3-term coarse error bound

// Output layout (float32, reference return order):
#define OFF_Q 1
#define OFF_P (1 + (size_t)N_TOKENS * EMBED)
#define OFF_E (2 + (size_t)N_TOKENS * EMBED)

__device__ __half  g_cb[2][K_CODES * EMBED];  // codebook fp16 split planes h/l
__device__ float   g_ncb[K_CODES * EMBED];    // f32 normalized codebook (fallback)
__device__ int     g_hist[K_CODES];
__device__ double  g_loss;

#define SW128(o) ((o) ^ (((o) >> 3) & 0x70))

__device__ __forceinline__ uint32_t smem_u32(const void* p) {
    uint32_t a;
    asm("{ .reg .u64 t; cvta.to.shared.u64 t, %1; cvt.u32.u64 %0, t; }"
        : "=r"(a) : "l"(p));
    return a;
}
__device__ __forceinline__ void ldsm4(uint32_t& r0, uint32_t& r1,
                                      uint32_t& r2, uint32_t& r3, uint32_t a) {
    asm volatile("ldmatrix.sync.aligned.m8n8.x4.shared.b16 {%0,%1,%2,%3}, [%4];"
                 : "=r"(r0), "=r"(r1), "=r"(r2), "=r"(r3) : "r"(a));
}
__device__ __forceinline__ void mma16816(float* d, const uint32_t* a,
                                         const uint32_t* b) {
    asm volatile(
        "mma.sync.aligned.m16n8k16.row.col.f32.f16.f16.f32 "
        "{%0,%1,%2,%3}, {%4,%5,%6,%7}, {%8,%9}, {%0,%1,%2,%3};"
        : "+f"(d[0]), "+f"(d[1]), "+f"(d[2]), "+f"(d[3])
        : "r"(a[0]), "r"(a[1]), "r"(a[2]), "r"(a[3]), "r"(b[0]), "r"(b[1]));
}

// ---------------------------------------------------------------------------
// Prep: normalize codebook; fp16 2-way split + f32 copy; zero hist/loss.
// ---------------------------------------------------------------------------
__global__ void k_prep(const float* __restrict__ weight)
{
    const int tid  = threadIdx.x;
    const int lane = tid & 31;
    const int k    = blockIdx.x * 8 + (tid >> 5);
    const int gid  = blockIdx.x * 256 + tid;

    if (gid == 0) g_loss = 0.0;
    if (gid < K_CODES) g_hist[gid] = 0;

    const float* wr = weight + (size_t)k * EMBED;
    float a = wr[lane], b = wr[lane + 32];
    float s = fmaf(a, a, b * b);
#pragma unroll
    for (int o = 16; o > 0; o >>= 1) s += __shfl_xor_sync(0xffffffffu, s, o);
    float dn = fmaxf(sqrtf(s), 1e-12f);

#pragma unroll
    for (int h = 0; h < 2; ++h) {
        int d = lane + 32 * h;
        float v = (h ? b : a) / dn;
        __half vh = __float2half_rn(v);
        float r1 = v - __half2float(vh);
        __half vl = __float2half_rn(r1);
        g_cb[0][(size_t)k * EMBED + d] = vh;
        g_cb[1][(size_t)k * EMBED + d] = vl;
        g_ncb[(size_t)k * EMBED + d]   = v;
    }
}

// ---------------------------------------------------------------------------
// Main: fp16x2 split-GEMM via mma.sync (3 terms: hh, hl, lh), coarse top-2
// per token, exact-f32 fallback for near-ties, fused epilogue.
// ---------------------------------------------------------------------------
extern __shared__ char smem_raw[];

__global__ void __launch_bounds__(THREADS, 2)
k_main(const float* __restrict__ inputs,
       const float* __restrict__ weight,
       float* __restrict__ out)
{
    __shared__ int s_best[TOK_TILE];
    __shared__ int s_flag[TOK_TILE];

    char* smem = (char*)(((uintptr_t)smem_raw + 1023) & ~(uintptr_t)1023);
    const uint32_t smb = smem_u32(smem);
    const int tid = threadIdx.x;
    const int wid = tid >> 5;
    const int lane = tid & 31;
    const int tokBase = blockIdx.x * TOK_TILE;

    // ---- phase 1: stage A (normalize, fp16 2-way split) into SW128 smem ----
    {
        const int t = tid >> 1, h = tid & 1;       // 2 threads per token
        const float4* zp = (const float4*)(inputs + (size_t)(tokBase + t) * EMBED + h * 32);
        float z[32];
        float s = 0.f;
#pragma unroll
        for (int i = 0; i < 8; ++i) {
            float4 v = zp[i];
            z[4*i+0]=v.x; z[4*i+1]=v.y; z[4*i+2]=v.z; z[4*i+3]=v.w;
            s = fmaf(v.x,v.x,s); s = fmaf(v.y,v.y,s);
            s = fmaf(v.z,v.z,s); s = fmaf(v.w,v.w,s);
        }
        s += __shfl_xor_sync(0xffffffffu, s, 1);
        float dn = fmaxf(sqrtf(s), 1e-12f);
#pragma unroll
        for (int g = 0; g < 4; ++g) {              // 4 x 16B granules
            unsigned short uh[8], ul[8];
#pragma unroll
            for (int j = 0; j < 8; ++j) {
                float v = z[g * 8 + j] / dn;
                __half vh = __float2half_rn(v);
                float r1 = v - __half2float(vh);
                __half vl = __float2half_rn(r1);
                uh[j] = __half_as_ushort(vh);
                ul[j] = __half_as_ushort(vl);
            }
            uint32_t off = SW128((uint32_t)(t * 128 + h * 64 + g * 16));
            *(uint4*)(smem + 0*PLANE_SZ + off) = *(uint4*)uh;
            *(uint4*)(smem + 1*PLANE_SZ + off) = *(uint4*)ul;
        }
    }
    __syncthreads();

    // ---- load A fragments into registers (2 planes x 4 k-steps x 4 regs) ----
    const int mi = lane >> 3, r8 = lane & 7;
    const int tig = lane & 3, lgid = lane >> 2;
    uint32_t af[2][16];
    {
        const int row = wid * 16 + (mi & 1) * 8 + r8;
        const uint32_t rowBase = smb + (uint32_t)row * 128;
#pragma unroll
        for (int p = 0; p < 2; ++p)
#pragma unroll
            for (int s = 0; s < 4; ++s) {
                int gran = 2 * s + (mi >> 1);
                ldsm4(af[p][4*s], af[p][4*s+1], af[p][4*s+2], af[p][4*s+3],
                      rowBase + p * PLANE_SZ + (uint32_t)((gran ^ r8) * 16));
            }
    }

    // per-lane top-2 for token rows lgid (A) and lgid+8 (B)
    float v1a = -2e30f, v2a = -3e30f, v1b = -2e30f, v2b = -3e30f;
    int   i1a = 0, i2a = 0, i1b = 0, i2b = 0;

#pragma unroll 1
    for (int ct = 0; ct < NCHUNK; ++ct) {
        __syncthreads();   // A frags read (ct==0) / previous chunk consumed
        for (int i = tid; i < 2 * NC * 8; i += THREADS) {
            int pl = i >> 10, rem = i & 1023, rr = rem >> 3, g = rem & 7;
            uint4 v = *(const uint4*)(&g_cb[pl][(size_t)(ct * NC + rr) * EMBED + g * 8]);
            *(uint4*)(smem + pl * PLANE_SZ + rr * 128 + ((g ^ (rr & 7)) * 16)) = v;
        }
        __syncthreads();

#pragma unroll 1
        for (int n0 = 0; n0 < NC; n0 += 8) {
            uint32_t bf[2][8];
            const uint32_t bBase = smb + (uint32_t)((n0 + r8) * 128);
#pragma unroll
            for (int p = 0; p < 2; ++p) {
                ldsm4(bf[p][0], bf[p][1], bf[p][2], bf[p][3],
                      bBase + p * PLANE_SZ + (uint32_t)((mi ^ r8) * 16));
                ldsm4(bf[p][4], bf[p][5], bf[p][6], bf[p][7],
                      bBase + p * PLANE_SZ + (uint32_t)(((4 + mi) ^ r8) * 16));
            }
            float accA[4] = {0,0,0,0}, accB[4] = {0,0,0,0}, accC[4] = {0,0,0,0};
#pragma unroll
            for (int s = 0; s < 4; ++s) {
                mma16816(accA, &af[0][4*s], &bf[0][2*s]);   // h*h
                mma16816(accB, &af[0][4*s], &bf[1][2*s]);   // h*l
                mma16816(accC, &af[1][4*s], &bf[0][2*s]);   // l*h
            }
            float s0 = accA[0] + accB[0] + accC[0];
            float s1 = accA[1] + accB[1] + accC[1];
            float s2 = accA[2] + accB[2] + accC[2];
            float s3 = accA[3] + accB[3] + accC[3];
            const int c0 = ct * NC + n0 + 2 * tig;
            // top-2 updates (ascending code order; strict > keeps first-occurrence)
            if (s0 > v1a)      { v2a = v1a; i2a = i1a; v1a = s0; i1a = c0;     }
            else if (s0 > v2a) { v2a = s0;  i2a = c0; }
            if (s1 > v1a)      { v2a = v1a; i2a = i1a; v1a = s1; i1a = c0 + 1; }
            else if (s1 > v2a) { v2a = s1;  i2a = c0 + 1; }
            if (s2 > v1b)      { v2b = v1b; i2b = i1b; v1b = s2; i1b = c0;     }
            else if (s2 > v2b) { v2b = s2;  i2b = c0; }
            if (s3 > v1b)      { v2b = v1b; i2b = i1b; v1b = s3; i1b = c0 + 1; }
            else if (s3 > v2b) { v2b = s3;  i2b = c0 + 1; }
        }
    }

    // ---- merge top-2 across the 4 tig-lanes sharing each token row ----
#pragma unroll
    for (int o = 1; o <= 2; o <<= 1) {
        float ov1 = __shfl_xor_sync(0xffffffffu, v1a, o);
        int   oi1 = __shfl_xor_sync(0xffffffffu, i1a, o);
        float ov2 = __shfl_xor_sync(0xffffffffu, v2a, o);
        int   oi2 = __shfl_xor_sync(0xffffffffu, i2a, o);
        if (ov1 > v1a || (ov1 == v1a && oi1 < i1a)) {
            float tv = v1a; int ti = i1a;
            v1a = ov1; i1a = oi1;
            if (ov2 > tv || (ov2 == tv && oi2 < ti)) { v2a = ov2; i2a = oi2; }
            else                                     { v2a = tv;  i2a = ti;  }
        } else {
            if (ov1 > v2a || (ov1 == v2a && oi1 < i2a)) { v2a = ov1; i2a = oi1; }
        }
        ov1 = __shfl_xor_sync(0xffffffffu, v1b, o);
        oi1 = __shfl_xor_sync(0xffffffffu, i1b, o);
        ov2 = __shfl_xor_sync(0xffffffffu, v2b, o);
        oi2 = __shfl_xor_sync(0xffffffffu, i2b, o);
        if (ov1 > v1b || (ov1 == v1b && oi1 < i1b)) {
            float tv = v1b; int ti = i1b;
            v1b = ov1; i1b = oi1;
            if (ov2 > tv || (ov2 == tv && oi2 < ti)) { v2b = ov2; i2b = oi2; }
            else                                     { v2b = tv;  i2b = ti;  }
        } else {
            if (ov1 > v2b || (ov1 == v2b && oi1 < i2b)) { v2b = ov1; i2b = oi1; }
        }
    }
    if (tig == 0) {
        s_best[wid * 16 + lgid]     = i1a;
        s_flag[wid * 16 + lgid]     = (v1a - v2a < MARGIN);
        s_best[wid * 16 + 8 + lgid] = i1b;
        s_flag[wid * 16 + 8 + lgid] = (v1b - v2b < MARGIN);
    }
    __syncwarp();

    // ---- exact-f32 fallback for near-ties (rare; cold path) ----
    float* zscr = (float*)(smem + SCRATCH) + wid * 64;
#pragma unroll 1
    for (int jj = 0; jj < 16; ++jj) {
        const int lt = wid * 16 + jj;
        if (!s_flag[lt]) continue;
        const int tok = tokBase + lt;
        float a = inputs[(size_t)tok * EMBED + lane];
        float b = inputs[(size_t)tok * EMBED + lane + 32];
        float s = fmaf(a, a, b * b);
#pragma unroll
        for (int o = 16; o > 0; o >>= 1) s += __shfl_xor_sync(0xffffffffu, s, o);
        float dn = fmaxf(sqrtf(s), 1e-12f);
        zscr[lane]      = a / dn;
        zscr[lane + 32] = b / dn;
        __syncwarp();
        float bv = -2e30f; int bi = 0;
        for (int c = 0; c < 32; ++c) {
            int code = lane + 32 * c;
            const float* cr = g_ncb + (size_t)code * EMBED;
            float d = 0.f;
#pragma unroll
            for (int i = 0; i < EMBED; ++i) d = fmaf(zscr[i], cr[i], d);
            if (d > bv) { bv = d; bi = code; }
        }
#pragma unroll
        for (int o = 16; o > 0; o >>= 1) {
            float ov = __shfl_xor_sync(0xffffffffu, bv, o);
            int   oi = __shfl_xor_sync(0xffffffffu, bi, o);
            if (ov > bv || (ov == bv && oi < bi)) { bv = ov; bi = oi; }
        }
        if (lane == 0) s_best[lt] = bi;
        __syncwarp();
    }
    __syncwarp();

    // ---- fused epilogue: 8 warps x 16 tokens (warp-local s_best) ----
    float* out_q   = out + OFF_Q;
    float* out_enc = out + OFF_E;
    float lsum = 0.f;

#pragma unroll 1
    for (int jj = 0; jj < 16; ++jj) {
        const int lt  = wid * 16 + jj;
        const int tok = tokBase + lt;
        const int bi  = s_best[lt];
        const float* wr = weight + (size_t)bi  * EMBED;
        const float* xr = inputs + (size_t)tok * EMBED;
        float q0 = wr[lane], q1 = wr[lane + 32];
        float x0 = xr[lane], x1 = xr[lane + 32];
        out_q[(size_t)tok * EMBED + lane]      = q0;
        out_q[(size_t)tok * EMBED + lane + 32] = q1;
        float d0 = q0 - x0, d1 = q1 - x1;
        lsum = fmaf(d0, d0, lsum);
        lsum = fmaf(d1, d1, lsum);

        // encodings base is float-offset ≡ 2 (mod 4) -> 8B-aligned: float2 only
        float2* erow = (float2*)(out_enc + (size_t)tok * K_CODES);
#pragma unroll
        for (int i = 0; i < 16; ++i) {
            int f2  = lane + 32 * i;
            int rel = bi - 2 * f2;
            float2 e;
            e.x = (rel == 0) ? 1.f : 0.f;
            e.y = (rel == 1) ? 1.f : 0.f;
            erow[f2] = e;
        }
    }

    if (lane == 0) {
        for (int jj = 0; jj < 16; ++jj)
            atomicAdd(&g_hist[s_best[wid * 16 + jj]], 1);
    }
#pragma unroll
    for (int o = 16; o > 0; o >>= 1)
        lsum += __shfl_xor_sync(0xffffffffu, lsum, o);
    if (lane == 0) atomicAdd(&g_loss, (double)lsum);
}

// ---------------------------------------------------------------------------
// Final: loss scalar + perplexity from histogram.   <<<1, 1024>>>
// ---------------------------------------------------------------------------
__global__ void k_final(float* __restrict__ out)
{
    __shared__ double sh[32];
    int tid = threadIdx.x, lane = tid & 31, w = tid >> 5;

    float p  = (float)g_hist[tid] / (float)N_TOKENS;
    double v = (double)(p * logf(p + 1e-10f));
#pragma unroll
    for (int o = 16; o > 0; o >>= 1) v += __shfl_xor_sync(0xffffffffu, v, o);
    if (lane == 0) sh[w] = v;
    __syncthreads();
    if (tid == 0) {
        double tot = 0.0;
#pragma unroll
        for (int i = 0; i < 32; ++i) tot += sh[i];
        out[0]     = (float)(1.25 * g_loss / (double)((size_t)N_TOKENS * EMBED));
        out[OFF_P] = expf(-(float)tot);
    }
}

// ---------------------------------------------------------------------------
extern "C" void kernel_launch(void* const* d_in, const int* in_sizes, int n_in,
                              void* d_out, int out_size)
{
    const float* inputs = (const float*)d_in[0];
    const float* weight = (const float*)d_in[1];
    float*       out    = (float*)d_out;

    cudaFuncSetAttribute(k_main, cudaFuncAttributeMaxDynamicSharedMemorySize,
                         SMEM_DYN);

    k_prep <<<K_CODES / 8, 256>>>(weight);
    k_main <<<N_TOKENS / TOK_TILE, THREADS, SMEM_DYN>>>(inputs, weight, out);
    k_final<<<1, K_CODES>>>(out);
}

// round 8
// speedup vs baseline: 2.0764x; 1.0348x over previous
#include <cuda_runtime.h>
#include <cuda_fp16.h>
#include <math.h>
#include <stdint.h>

#define N_TOKENS 131072
#define EMBED    64
#define K_CODES  1024
#define TOK_TILE 128           // tokens per CTA
#define NC       128           // codes per smem chunk
#define NCHUNK   (K_CODES / NC)
#define THREADS  256
#define PLANE_SZ 16384         // 128 rows x 128 B
#define SCRATCH  (2 * PLANE_SZ)            // fallback z scratch (8 warps x 64 f32)
#define SMEM_DYN (2 * PLANE_SZ + 2048 + 1024)
#define MARGIN   8e-6f         // > 8x rigorous fp16-3-term coarse error bound

// Output layout (float32, reference return order):
#define OFF_Q 1
#define OFF_P (1 + (size_t)N_TOKENS * EMBED)
#define OFF_E (2 + (size_t)N_TOKENS * EMBED)

__device__ __half  g_cb[2][K_CODES * EMBED];  // codebook fp16 split planes h/l
__device__ float   g_ncb[K_CODES * EMBED];    // f32 normalized codebook (fallback)
__device__ int     g_hist[K_CODES];
__device__ double  g_loss;

#define SW128(o) ((o) ^ (((o) >> 3) & 0x70))

__device__ __forceinline__ uint32_t smem_u32(const void* p) {
    uint32_t a;
    asm("{ .reg .u64 t; cvta.to.shared.u64 t, %1; cvt.u32.u64 %0, t; }"
        : "=r"(a) : "l"(p));
    return a;
}
__device__ __forceinline__ void ldsm4(uint32_t& r0, uint32_t& r1,
                                      uint32_t& r2, uint32_t& r3, uint32_t a) {
    asm volatile("ldmatrix.sync.aligned.m8n8.x4.shared.b16 {%0,%1,%2,%3}, [%4];"
                 : "=r"(r0), "=r"(r1), "=r"(r2), "=r"(r3) : "r"(a));
}
__device__ __forceinline__ void mma16816(float* d, const uint32_t* a,
                                         const uint32_t* b) {
    asm volatile(
        "mma.sync.aligned.m16n8k16.row.col.f32.f16.f16.f32 "
        "{%0,%1,%2,%3}, {%4,%5,%6,%7}, {%8,%9}, {%0,%1,%2,%3};"
        : "+f"(d[0]), "+f"(d[1]), "+f"(d[2]), "+f"(d[3])
        : "r"(a[0]), "r"(a[1]), "r"(a[2]), "r"(a[3]), "r"(b[0]), "r"(b[1]));
}

// branchless top-2 (value-only second place); ascending scan keeps
// first-occurrence on ties via strict >
__device__ __forceinline__ void top2_upd(float s, int c,
                                         float& v1, int& i1, float& v2) {
    v2 = fmaxf(v2, fminf(v1, s));
    i1 = (s > v1) ? c : i1;
    v1 = fmaxf(v1, s);
}

// ---------------------------------------------------------------------------
// Prep: normalize codebook; fp16 2-way split + f32 copy; zero hist/loss.
// ---------------------------------------------------------------------------
__global__ void k_prep(const float* __restrict__ weight)
{
    const int tid  = threadIdx.x;
    const int lane = tid & 31;
    const int k    = blockIdx.x * 8 + (tid >> 5);
    const int gid  = blockIdx.x * 256 + tid;

    if (gid == 0) g_loss = 0.0;
    if (gid < K_CODES) g_hist[gid] = 0;

    const float* wr = weight + (size_t)k * EMBED;
    float a = wr[lane], b = wr[lane + 32];
    float s = fmaf(a, a, b * b);
#pragma unroll
    for (int o = 16; o > 0; o >>= 1) s += __shfl_xor_sync(0xffffffffu, s, o);
    float dn = fmaxf(sqrtf(s), 1e-12f);

#pragma unroll
    for (int h = 0; h < 2; ++h) {
        int d = lane + 32 * h;
        float v = (h ? b : a) / dn;
        __half vh = __float2half_rn(v);
        float r1 = v - __half2float(vh);
        __half vl = __float2half_rn(r1);
        g_cb[0][(size_t)k * EMBED + d] = vh;
        g_cb[1][(size_t)k * EMBED + d] = vl;
        g_ncb[(size_t)k * EMBED + d]   = v;
    }
}

// ---------------------------------------------------------------------------
// Main: fp16x2 split-GEMM via mma.sync (3 terms: hh, hl, lh), branchless
// top-2, exact-f32 fallback for near-ties, fused epilogue.
// ---------------------------------------------------------------------------
extern __shared__ char smem_raw[];

__global__ void __launch_bounds__(THREADS, 2)
k_main(const float* __restrict__ inputs,
       const float* __restrict__ weight,
       float* __restrict__ out)
{
    __shared__ int s_best[TOK_TILE];
    __shared__ int s_flag[TOK_TILE];

    char* smem = (char*)(((uintptr_t)smem_raw + 1023) & ~(uintptr_t)1023);
    const uint32_t smb = smem_u32(smem);
    const int tid = threadIdx.x;
    const int wid = tid >> 5;
    const int lane = tid & 31;
    const int tokBase = blockIdx.x * TOK_TILE;

    // ---- phase 1: stage A (normalize, fp16 2-way split) into SW128 smem ----
    {
        const int t = tid >> 1, h = tid & 1;       // 2 threads per token
        const float4* zp = (const float4*)(inputs + (size_t)(tokBase + t) * EMBED + h * 32);
        float z[32];
        float s = 0.f;
#pragma unroll
        for (int i = 0; i < 8; ++i) {
            float4 v = zp[i];
            z[4*i+0]=v.x; z[4*i+1]=v.y; z[4*i+2]=v.z; z[4*i+3]=v.w;
            s = fmaf(v.x,v.x,s); s = fmaf(v.y,v.y,s);
            s = fmaf(v.z,v.z,s); s = fmaf(v.w,v.w,s);
        }
        s += __shfl_xor_sync(0xffffffffu, s, 1);
        float dn = fmaxf(sqrtf(s), 1e-12f);
#pragma unroll
        for (int g = 0; g < 4; ++g) {              // 4 x 16B granules
            unsigned short uh[8], ul[8];
#pragma unroll
            for (int j = 0; j < 8; ++j) {
                float v = z[g * 8 + j] / dn;
                __half vh = __float2half_rn(v);
                float r1 = v - __half2float(vh);
                __half vl = __float2half_rn(r1);
                uh[j] = __half_as_ushort(vh);
                ul[j] = __half_as_ushort(vl);
            }
            uint32_t off = SW128((uint32_t)(t * 128 + h * 64 + g * 16));
            *(uint4*)(smem + 0*PLANE_SZ + off) = *(uint4*)uh;
            *(uint4*)(smem + 1*PLANE_SZ + off) = *(uint4*)ul;
        }
    }
    __syncthreads();

    // ---- load A fragments into registers (2 planes x 4 k-steps x 4 regs) ----
    const int mi = lane >> 3, r8 = lane & 7;
    const int tig = lane & 3, lgid = lane >> 2;
    uint32_t af[2][16];
    {
        const int row = wid * 16 + (mi & 1) * 8 + r8;
        const uint32_t rowBase = smb + (uint32_t)row * 128;
#pragma unroll
        for (int p = 0; p < 2; ++p)
#pragma unroll
            for (int s = 0; s < 4; ++s) {
                int gran = 2 * s + (mi >> 1);
                ldsm4(af[p][4*s], af[p][4*s+1], af[p][4*s+2], af[p][4*s+3],
                      rowBase + p * PLANE_SZ + (uint32_t)((gran ^ r8) * 16));
            }
    }

    // per-lane top-2 for token rows lgid (A) and lgid+8 (B); v2 = value only
    float v1a = -2e30f, v2a = -3e30f, v1b = -2e30f, v2b = -3e30f;
    int   i1a = 0, i1b = 0;

#pragma unroll 1
    for (int ct = 0; ct < NCHUNK; ++ct) {
        __syncthreads();   // A frags read (ct==0) / previous chunk consumed
        for (int i = tid; i < 2 * NC * 8; i += THREADS) {
            int pl = i >> 10, rem = i & 1023, rr = rem >> 3, g = rem & 7;
            uint4 v = *(const uint4*)(&g_cb[pl][(size_t)(ct * NC + rr) * EMBED + g * 8]);
            *(uint4*)(smem + pl * PLANE_SZ + rr * 128 + ((g ^ (rr & 7)) * 16)) = v;
        }
        __syncthreads();

#pragma unroll 1
        for (int n0 = 0; n0 < NC; n0 += 8) {
            uint32_t bf[2][8];
            const uint32_t bBase = smb + (uint32_t)((n0 + r8) * 128);
#pragma unroll
            for (int p = 0; p < 2; ++p) {
                ldsm4(bf[p][0], bf[p][1], bf[p][2], bf[p][3],
                      bBase + p * PLANE_SZ + (uint32_t)((mi ^ r8) * 16));
                ldsm4(bf[p][4], bf[p][5], bf[p][6], bf[p][7],
                      bBase + p * PLANE_SZ + (uint32_t)(((4 + mi) ^ r8) * 16));
            }
            float accA[4] = {0,0,0,0}, accB[4] = {0,0,0,0}, accC[4] = {0,0,0,0};
#pragma unroll
            for (int s = 0; s < 4; ++s) {
                mma16816(accA, &af[0][4*s], &bf[0][2*s]);   // h*h
                mma16816(accB, &af[0][4*s], &bf[1][2*s]);   // h*l
                mma16816(accC, &af[1][4*s], &bf[0][2*s]);   // l*h
            }
            float s0 = accA[0] + accB[0] + accC[0];
            float s1 = accA[1] + accB[1] + accC[1];
            float s2 = accA[2] + accB[2] + accC[2];
            float s3 = accA[3] + accB[3] + accC[3];
            const int c0 = ct * NC + n0 + 2 * tig;
            top2_upd(s0, c0,     v1a, i1a, v2a);
            top2_upd(s1, c0 + 1, v1a, i1a, v2a);
            top2_upd(s2, c0,     v1b, i1b, v2b);
            top2_upd(s3, c0 + 1, v1b, i1b, v2b);
        }
    }

    // ---- branchless top-2 merge across the 4 tig-lanes per token row ----
#pragma unroll
    for (int o = 1; o <= 2; o <<= 1) {
        float ov1 = __shfl_xor_sync(0xffffffffu, v1a, o);
        int   oi1 = __shfl_xor_sync(0xffffffffu, i1a, o);
        float ov2 = __shfl_xor_sync(0xffffffffu, v2a, o);
        {
            float lo = fminf(v1a, ov1);
            v2a = fmaxf(fmaxf(v2a, ov2), lo);
            bool take = (ov1 > v1a) || (ov1 == v1a && oi1 < i1a);
            i1a = take ? oi1 : i1a;
            v1a = fmaxf(v1a, ov1);
        }
        ov1 = __shfl_xor_sync(0xffffffffu, v1b, o);
        oi1 = __shfl_xor_sync(0xffffffffu, i1b, o);
        ov2 = __shfl_xor_sync(0xffffffffu, v2b, o);
        {
            float lo = fminf(v1b, ov1);
            v2b = fmaxf(fmaxf(v2b, ov2), lo);
            bool take = (ov1 > v1b) || (ov1 == v1b && oi1 < i1b);
            i1b = take ? oi1 : i1b;
            v1b = fmaxf(v1b, ov1);
        }
    }
    if (tig == 0) {
        s_best[wid * 16 + lgid]     = i1a;
        s_flag[wid * 16 + lgid]     = (v1a - v2a < MARGIN);
        s_best[wid * 16 + 8 + lgid] = i1b;
        s_flag[wid * 16 + 8 + lgid] = (v1b - v2b < MARGIN);
    }
    __syncwarp();

    // ---- exact-f32 fallback for near-ties (rare; cold path) ----
    float* zscr = (float*)(smem + SCRATCH) + wid * 64;
#pragma unroll 1
    for (int jj = 0; jj < 16; ++jj) {
        const int lt = wid * 16 + jj;
        if (!s_flag[lt]) continue;
        const int tok = tokBase + lt;
        float a = inputs[(size_t)tok * EMBED + lane];
        float b = inputs[(size_t)tok * EMBED + lane + 32];
        float s = fmaf(a, a, b * b);
#pragma unroll
        for (int o = 16; o > 0; o >>= 1) s += __shfl_xor_sync(0xffffffffu, s, o);
        float dn = fmaxf(sqrtf(s), 1e-12f);
        zscr[lane]      = a / dn;
        zscr[lane + 32] = b / dn;
        __syncwarp();
        float bv = -2e30f; int bi = 0;
        for (int c = 0; c < 32; ++c) {
            int code = lane + 32 * c;
            const float* cr = g_ncb + (size_t)code * EMBED;
            float d = 0.f;
#pragma unroll
            for (int i = 0; i < EMBED; ++i) d = fmaf(zscr[i], cr[i], d);
            if (d > bv) { bv = d; bi = code; }
        }
#pragma unroll
        for (int o = 16; o > 0; o >>= 1) {
            float ov = __shfl_xor_sync(0xffffffffu, bv, o);
            int   oi = __shfl_xor_sync(0xffffffffu, bi, o);
            if (ov > bv || (ov == bv && oi < bi)) { bv = ov; bi = oi; }
        }
        if (lane == 0) s_best[lt] = bi;
        __syncwarp();
    }
    __syncwarp();

    // ---- fused epilogue: 8 warps x 16 tokens (warp-local s_best) ----
    float* out_q   = out + OFF_Q;
    float* out_enc = out + OFF_E;
    float lsum = 0.f;

#pragma unroll 1
    for (int jj = 0; jj < 16; ++jj) {
        const int lt  = wid * 16 + jj;
        const int tok = tokBase + lt;
        const int bi  = s_best[lt];
        const float* wr = weight + (size_t)bi  * EMBED;
        const float* xr = inputs + (size_t)tok * EMBED;
        float q0 = wr[lane], q1 = wr[lane + 32];
        float x0 = xr[lane], x1 = xr[lane + 32];
        out_q[(size_t)tok * EMBED + lane]      = q0;
        out_q[(size_t)tok * EMBED + lane + 32] = q1;
        float d0 = q0 - x0, d1 = q1 - x1;
        lsum = fmaf(d0, d0, lsum);
        lsum = fmaf(d1, d1, lsum);

        // encodings base is float-offset ≡ 2 (mod 4) -> 8B-aligned: float2 only
        float2* erow = (float2*)(out_enc + (size_t)tok * K_CODES);
#pragma unroll
        for (int i = 0; i < 16; ++i) {
            int f2  = lane + 32 * i;
            int rel = bi - 2 * f2;
            float2 e;
            e.x = (rel == 0) ? 1.f : 0.f;
            e.y = (rel == 1) ? 1.f : 0.f;
            erow[f2] = e;
        }
    }

    if (lane == 0) {
        for (int jj = 0; jj < 16; ++jj)
            atomicAdd(&g_hist[s_best[wid * 16 + jj]], 1);
    }
#pragma unroll
    for (int o = 16; o > 0; o >>= 1)
        lsum += __shfl_xor_sync(0xffffffffu, lsum, o);
    if (lane == 0) atomicAdd(&g_loss, (double)lsum);
}

// ---------------------------------------------------------------------------
// Final: loss scalar + perplexity from histogram.   <<<1, 1024>>>
// ---------------------------------------------------------------------------
__global__ void k_final(float* __restrict__ out)
{
    __shared__ double sh[32];
    int tid = threadIdx.x, lane = tid & 31, w = tid >> 5;

    float p  = (float)g_hist[tid] / (float)N_TOKENS;
    double v = (double)(p * logf(p + 1e-10f));
#pragma unroll
    for (int o = 16; o > 0; o >>= 1) v += __shfl_xor_sync(0xffffffffu, v, o);
    if (lane == 0) sh[w] = v;
    __syncthreads();
    if (tid == 0) {
        double tot = 0.0;
#pragma unroll
        for (int i = 0; i < 32; ++i) tot += sh[i];
        out[0]     = (float)(1.25 * g_loss / (double)((size_t)N_TOKENS * EMBED));
        out[OFF_P] = expf(-(float)tot);
    }
}

// ---------------------------------------------------------------------------
extern "C" void kernel_launch(void* const* d_in, const int* in_sizes, int n_in,
                              void* d_out, int out_size)
{
    const float* inputs = (const float*)d_in[0];
    const float* weight = (const float*)d_in[1];
    float*       out    = (float*)d_out;

    cudaFuncSetAttribute(k_main, cudaFuncAttributeMaxDynamicSharedMemorySize,
                         SMEM_DYN);

    k_prep <<<K_CODES / 8, 256>>>(weight);
    k_main <<<N_TOKENS / TOK_TILE, THREADS, SMEM_DYN>>>(inputs, weight, out);
    k_final<<<1, K_CODES>>>(out);
}